// round 16
// baseline (speedup 1.0000x reference)
#include <cuda_runtime.h>
#include <math.h>

#define NROWS  8192
#define DIM    512
#define NTRIP  200000
#define GRID   1184                    // 8 blocks/SM x 148 SMs, one wave at 32 regs
#define WARPS  (GRID * 8)
#define CHUNK  22                      // ceil(NTRIP / WARPS)

// Scratch (no allocations allowed in kernel_launch)
__device__ float        g_xn[NROWS];
__device__ float        g_sc[NROWS];
__device__ double       g_acc;
__device__ unsigned int g_done;
__device__ int          g_xq[NROWS * DIM / 4];   // 4 MB int8 table
__device__ unsigned int g_hist[NROWS];           // anchor histogram (zeroed by scan)
__device__ unsigned int g_cur[NROWS];            // scatter cursors (written by scan)
__device__ uint4        g_ts[NTRIP];             // sorted triplets {a,p,n,0}

// ---------------------------------------------------------------------------
// helper: per-block triplet dtype detect (int64 little-endian idx<8192 ->
// every odd 32-bit word zero)
// ---------------------------------------------------------------------------
__device__ __forceinline__ int detect_is64(const unsigned int* tw) {
    int all_zero = 1;
    for (int i = 1; i < 96; i += 2)
        if (tw[i] != 0u) { all_zero = 0; break; }
    return all_zero;
}

// ---------------------------------------------------------------------------
// Kernel 1: prep (norm/max + int8 quantize, warp per row) + anchor histogram.
// ---------------------------------------------------------------------------
__global__ void prep_kernel(const float* __restrict__ x,
                            const void* __restrict__ trip_raw) {
    __shared__ int s_is64;
    if (threadIdx.x == 0) {
        if (blockIdx.x == 0) { g_acc = 0.0; g_done = 0u; }
        s_is64 = detect_is64((const unsigned int*)trip_raw);
    }
    __syncthreads();

    int lane = threadIdx.x & 31;
    int row  = (blockIdx.x * blockDim.x + threadIdx.x) >> 5;

    if (row < NROWS) {
        const float4* rf = (const float4*)(x + (size_t)row * DIM);
        float4 v[4];
        float s = 0.f, m = 0.f;
#pragma unroll
        for (int k = 0; k < 4; k++) {
            v[k] = __ldg(&rf[lane + 32 * k]);
            s += v[k].x * v[k].x + v[k].y * v[k].y + v[k].z * v[k].z + v[k].w * v[k].w;
            m = fmaxf(m, fmaxf(fmaxf(fabsf(v[k].x), fabsf(v[k].y)),
                               fmaxf(fabsf(v[k].z), fabsf(v[k].w))));
        }
#pragma unroll
        for (int o = 16; o; o >>= 1) {
            s += __shfl_xor_sync(0xFFFFFFFFu, s, o);
            m = fmaxf(m, __shfl_xor_sync(0xFFFFFFFFu, m, o));
        }
        float scale = (m > 0.f) ? (m / 127.f) : 1.f;
        float inv   = (m > 0.f) ? (127.f / m) : 0.f;
        if (lane == 0) { g_xn[row] = s; g_sc[row] = scale; }

        int* qrow = g_xq + (size_t)row * (DIM / 4);
#pragma unroll
        for (int k = 0; k < 4; k++) {
            int qx = __float2int_rn(v[k].x * inv);
            int qy = __float2int_rn(v[k].y * inv);
            int qz = __float2int_rn(v[k].z * inv);
            int qw = __float2int_rn(v[k].w * inv);
            unsigned int packed = (unsigned int)(qx & 0xFF)
                                | ((unsigned int)(qy & 0xFF) << 8)
                                | ((unsigned int)(qz & 0xFF) << 16)
                                | ((unsigned int)(qw & 0xFF) << 24);
            qrow[lane + 32 * k] = (int)packed;
        }
    }

    // anchor histogram (g_hist was zeroed by last replay's scan; zero at init)
    int gt = blockIdx.x * blockDim.x + threadIdx.x;
    if (gt < NTRIP) {
        unsigned int a;
        if (s_is64) a = (unsigned int)__ldg(&((const long long*)trip_raw)[3 * gt]);
        else        a = (unsigned int)__ldg(&((const int*)trip_raw)[3 * gt]);
        atomicAdd(&g_hist[a], 1u);
    }
}

// ---------------------------------------------------------------------------
// Kernel 2: exclusive scan of 8192 bins (1 block, 1024 threads, 8 bins each).
// Also zeroes g_hist for the next replay.
// ---------------------------------------------------------------------------
__global__ void scan_kernel() {
    __shared__ unsigned int sh[1024];
    int tid = threadIdx.x;

    unsigned int h[8], s = 0;
#pragma unroll
    for (int j = 0; j < 8; j++) {
        h[j] = g_hist[tid * 8 + j];
        g_hist[tid * 8 + j] = 0u;          // reset for next replay
        s += h[j];
    }
    sh[tid] = s;
    __syncthreads();

    for (int off = 1; off < 1024; off <<= 1) {
        unsigned int v = (tid >= off) ? sh[tid - off] : 0u;
        __syncthreads();
        sh[tid] += v;
        __syncthreads();
    }

    unsigned int base = sh[tid] - s;       // exclusive prefix
#pragma unroll
    for (int j = 0; j < 8; j++) {
        g_cur[tid * 8 + j] = base;
        base += h[j];
    }
}

// ---------------------------------------------------------------------------
// Kernel 3: scatter triplets into anchor-sorted order.
// ---------------------------------------------------------------------------
__global__ void scatter_kernel(const void* __restrict__ trip_raw) {
    __shared__ int s_is64;
    if (threadIdx.x == 0)
        s_is64 = detect_is64((const unsigned int*)trip_raw);
    __syncthreads();

    int t = blockIdx.x * blockDim.x + threadIdx.x;
    if (t >= NTRIP) return;

    unsigned int a, p, n;
    if (s_is64) {
        const long long* t64 = (const long long*)trip_raw;
        a = (unsigned int)__ldg(&t64[3 * t + 0]);
        p = (unsigned int)__ldg(&t64[3 * t + 1]);
        n = (unsigned int)__ldg(&t64[3 * t + 2]);
    } else {
        const int* t32 = (const int*)trip_raw;
        a = (unsigned int)__ldg(&t32[3 * t + 0]);
        p = (unsigned int)__ldg(&t32[3 * t + 1]);
        n = (unsigned int)__ldg(&t32[3 * t + 2]);
    }
    unsigned int pos = atomicAdd(&g_cur[a], 1u);
    g_ts[pos] = make_uint4(a, p, n, 0u);
}

// ---------------------------------------------------------------------------
// Kernel 4: trip — 8-lane groups, 4 triplets/warp/iter over a CONTIGUOUS
// chunk of sorted triplets (anchor-row loads repeat -> L1 hits).
// Chunked gathers keep regs <= 32 -> 8 blocks/SM, single wave.
// ---------------------------------------------------------------------------
__global__ void __launch_bounds__(256, 8) trip_kernel(float* __restrict__ out)
{
    const int lane  = threadIdx.x & 31;
    const int grp   = lane >> 3;
    const int sub   = lane & 7;
    const int wib   = threadIdx.x >> 5;
    const int wpb   = blockDim.x >> 5;
    const int gwarp = blockIdx.x * wpb + wib;

    const uint4* xq = (const uint4*)g_xq;         // 32 uint4 per row
    float wsum = 0.f;

    const int t0   = gwarp * CHUNK;
    const int tend = (t0 + CHUNK < NTRIP) ? (t0 + CHUNK) : NTRIP;

    for (int j = 0; j < CHUNK; j += 4) {
        int t = t0 + j + grp;
        const int valid = (t < tend);
        int tc = valid ? t : 0;

        uint4 idx = __ldg(&g_ts[tc]);
        const unsigned int a = idx.x, p = idx.y, n = idx.z;

        unsigned int oa = a * 32u + sub;
        unsigned int op = p * 32u + sub;
        unsigned int on = n * 32u + sub;

        int iap = 0, ian = 0;
#pragma unroll
        for (int c = 0; c < 4; c++) {
            uint4 qa = __ldg(&xq[oa + 8u * c]);
            uint4 qp = __ldg(&xq[op + 8u * c]);
            uint4 qn = __ldg(&xq[on + 8u * c]);
            iap = __dp4a((int)qa.x, (int)qp.x, iap);
            ian = __dp4a((int)qa.x, (int)qn.x, ian);
            iap = __dp4a((int)qa.y, (int)qp.y, iap);
            ian = __dp4a((int)qa.y, (int)qn.y, ian);
            iap = __dp4a((int)qa.z, (int)qp.z, iap);
            ian = __dp4a((int)qa.z, (int)qn.z, ian);
            iap = __dp4a((int)qa.w, (int)qp.w, iap);
            ian = __dp4a((int)qa.w, (int)qn.w, ian);
        }

#pragma unroll
        for (int o = 4; o; o >>= 1) {
            iap += __shfl_xor_sync(0xFFFFFFFFu, iap, o);
            ian += __shfl_xor_sync(0xFFFFFFFFu, ian, o);
        }

        if (sub == 0 && valid) {
            float sa = g_sc[a];
            float dot_ap = sa * g_sc[p] * (float)iap;
            float dot_an = sa * g_sc[n] * (float)ian;
            float xna = g_xn[a];
            float dap = fmaxf(xna + g_xn[p] - 2.f * dot_ap, 0.f);
            float dan = fmaxf(xna + g_xn[n] - 2.f * dot_an, 0.f);
            float z = dap - dan;
            float sp = (z > 0.f) ? (z + log1pf(expf(-z))) : log1pf(expf(z));
            wsum += sp;
        }
    }

    wsum += __shfl_xor_sync(0xFFFFFFFFu, wsum, 8);
    wsum += __shfl_xor_sync(0xFFFFFFFFu, wsum, 16);

    __shared__ float ssum[8];
    if (lane == 0) ssum[wib] = wsum;
    __syncthreads();
    if (threadIdx.x == 0) {
        float bs = 0.f;
        for (int i = 0; i < wpb; i++) bs += ssum[i];
        atomicAdd(&g_acc, (double)bs);
        __threadfence();
        unsigned int ticket = atomicAdd(&g_done, 1u);
        if (ticket == gridDim.x - 1) {
            double total = atomicAdd(&g_acc, 0.0);
            out[0] = (float)(total / (double)NTRIP);
        }
    }
}

extern "C" void kernel_launch(void* const* d_in, const int* in_sizes, int n_in,
                              void* d_out, int out_size) {
    // Resolve input ordering by element count (x: 4194304, trip: 600000)
    const float* x;
    const void*  trip;
    if (in_sizes[0] == NROWS * DIM) { x = (const float*)d_in[0]; trip = d_in[1]; }
    else                            { x = (const float*)d_in[1]; trip = d_in[0]; }

    float* out = (float*)d_out;

    prep_kernel<<<NROWS / 8, 256>>>(x, trip);
    scan_kernel<<<1, 1024>>>();
    scatter_kernel<<<(NTRIP + 255) / 256, 256>>>(trip);
    trip_kernel<<<GRID, 256>>>(out);
}

// round 17
// speedup vs baseline: 1.5566x; 1.5566x over previous
#include <cuda_runtime.h>
#include <math.h>

#define NROWS  8192
#define DIM    512
#define NTRIP  200000
#define GRID   1184    // 8 blocks/SM x 148 SMs: fully resident -> grid barrier is safe

// Scratch (no allocations allowed in kernel_launch)
__device__ float2       g_xs[NROWS];             // {xn, scale} packed
__device__ double       g_acc;                   // zero-init; reset by last block
__device__ unsigned int g_done;                  // ticket counter
__device__ unsigned int g_sync;                  // grid barrier counter
__device__ int          g_xq[NROWS * DIM / 4];   // 4 MB int8 table (packed s8x4)

// ---------------------------------------------------------------------------
// Fused persistent kernel:
//   phase 1: warp-per-row int8 quantize + {norm, scale} -> g_xq / g_xs
//   grid barrier (all 1184 blocks resident by __launch_bounds__(256,8))
//   phase 2: 8-lane-group gather + dp4a dual dots + softplus, grid-stride
//   last block: writes out[0], resets counters for next graph replay
// ---------------------------------------------------------------------------
__global__ void __launch_bounds__(256, 8) fused_kernel(
    const float* __restrict__ x,
    const void*  __restrict__ trip_raw,
    float*       __restrict__ out)
{
    const int tid  = threadIdx.x;
    const int lane = tid & 31;
    const int wib  = tid >> 5;                    // warp in block (0..7)
    const int gwarp = blockIdx.x * 8 + wib;       // 0..9471

    __shared__ int   s_is64;
    __shared__ float ssum[8];

    // triplet dtype detect (int64 LE with idx<8192 -> odd 32-bit words all 0)
    if (tid == 0) {
        const unsigned int* tw = (const unsigned int*)trip_raw;
        int all_zero = 1;
        for (int i = 1; i < 96; i += 2)
            if (tw[i] != 0u) { all_zero = 0; break; }
        s_is64 = all_zero;
    }

    // ---------------- phase 1: quantize (rows 0..8191) ----------------
    if (gwarp < NROWS) {
        const int row = gwarp;
        const float4* rf = (const float4*)(x + (size_t)row * DIM);

        float4 v[4];
        float s = 0.f, m = 0.f;
#pragma unroll
        for (int k = 0; k < 4; k++) {
            v[k] = __ldg(&rf[lane + 32 * k]);
            s += v[k].x * v[k].x + v[k].y * v[k].y + v[k].z * v[k].z + v[k].w * v[k].w;
            m = fmaxf(m, fmaxf(fmaxf(fabsf(v[k].x), fabsf(v[k].y)),
                               fmaxf(fabsf(v[k].z), fabsf(v[k].w))));
        }
#pragma unroll
        for (int o = 16; o; o >>= 1) {
            s += __shfl_xor_sync(0xFFFFFFFFu, s, o);
            m = fmaxf(m, __shfl_xor_sync(0xFFFFFFFFu, m, o));
        }
        float scale = (m > 0.f) ? (m / 127.f) : 1.f;
        float inv   = (m > 0.f) ? (127.f / m) : 0.f;
        if (lane == 0) g_xs[row] = make_float2(s, scale);

        int* qrow = g_xq + (size_t)row * (DIM / 4);
#pragma unroll
        for (int k = 0; k < 4; k++) {
            int qx = __float2int_rn(v[k].x * inv);
            int qy = __float2int_rn(v[k].y * inv);
            int qz = __float2int_rn(v[k].z * inv);
            int qw = __float2int_rn(v[k].w * inv);
            unsigned int packed = (unsigned int)(qx & 0xFF)
                                | ((unsigned int)(qy & 0xFF) << 8)
                                | ((unsigned int)(qz & 0xFF) << 16)
                                | ((unsigned int)(qw & 0xFF) << 24);
            qrow[lane + 32 * k] = (int)packed;
        }
    }

    // ---------------- grid barrier (all blocks resident) ----------------
    __syncthreads();
    if (tid == 0) {
        __threadfence();                          // publish phase-1 stores
        atomicAdd(&g_sync, 1u);
        while (atomicAdd(&g_sync, 0u) < (unsigned)GRID) __nanosleep(64);
    }
    __syncthreads();

    // ---------------- phase 2: triplet loop ----------------
    const int grp = lane >> 3;                    // 0..3
    const int sub = lane & 7;                     // 0..7

    const int is64 = s_is64;
    const long long* t64 = (const long long*)trip_raw;
    const int*       t32 = (const int*)trip_raw;

    const uint4* xq = (const uint4*)g_xq;         // 32 uint4 per row
    float wsum = 0.f;                             // meaningful on sub==0 lanes

    const int nwarp = GRID * 8;
    for (int base = gwarp * 4; base < NTRIP; base += nwarp * 4) {
        int t = base + grp;
        const int valid = (t < NTRIP);
        int tc = valid ? t : (NTRIP - 1);

        int a, p, n;
        if (is64) {
            a = (int)__ldg(&t64[3 * tc + 0]);
            p = (int)__ldg(&t64[3 * tc + 1]);
            n = (int)__ldg(&t64[3 * tc + 2]);
        } else {
            a = __ldg(&t32[3 * tc + 0]);
            p = __ldg(&t32[3 * tc + 1]);
            n = __ldg(&t32[3 * tc + 2]);
        }

        unsigned int oa = (unsigned int)a * 32u + sub;
        unsigned int op = (unsigned int)p * 32u + sub;
        unsigned int on = (unsigned int)n * 32u + sub;

        int iap = 0, ian = 0;
#pragma unroll
        for (int c = 0; c < 4; c++) {
            uint4 qa = __ldg(&xq[oa + 8u * c]);
            uint4 qp = __ldg(&xq[op + 8u * c]);
            uint4 qn = __ldg(&xq[on + 8u * c]);
            iap = __dp4a((int)qa.x, (int)qp.x, iap);
            ian = __dp4a((int)qa.x, (int)qn.x, ian);
            iap = __dp4a((int)qa.y, (int)qp.y, iap);
            ian = __dp4a((int)qa.y, (int)qn.y, ian);
            iap = __dp4a((int)qa.z, (int)qp.z, iap);
            ian = __dp4a((int)qa.z, (int)qn.z, ian);
            iap = __dp4a((int)qa.w, (int)qp.w, iap);
            ian = __dp4a((int)qa.w, (int)qn.w, ian);
        }

#pragma unroll
        for (int o = 4; o; o >>= 1) {
            iap += __shfl_xor_sync(0xFFFFFFFFu, iap, o);
            ian += __shfl_xor_sync(0xFFFFFFFFu, ian, o);
        }

        if (sub == 0 && valid) {
            float2 xsa = __ldg(&g_xs[a]);
            float2 xsp = __ldg(&g_xs[p]);
            float2 xsn = __ldg(&g_xs[n]);
            float dot_ap = xsa.y * xsp.y * (float)iap;
            float dot_an = xsa.y * xsn.y * (float)ian;
            float dap = fmaxf(xsa.x + xsp.x - 2.f * dot_ap, 0.f);
            float dan = fmaxf(xsa.x + xsn.x - 2.f * dot_an, 0.f);
            float z = dap - dan;
            float sp = (z > 0.f) ? (z + log1pf(expf(-z))) : log1pf(expf(z));
            wsum += sp;
        }
    }

    // combine 4 group sums (lanes 0,8,16,24)
    wsum += __shfl_xor_sync(0xFFFFFFFFu, wsum, 8);
    wsum += __shfl_xor_sync(0xFFFFFFFFu, wsum, 16);

    if (lane == 0) ssum[wib] = wsum;
    __syncthreads();
    if (tid == 0) {
        float bs = 0.f;
        for (int i = 0; i < 8; i++) bs += ssum[i];
        atomicAdd(&g_acc, (double)bs);
        __threadfence();
        unsigned int ticket = atomicAdd(&g_done, 1u);
        if (ticket == (unsigned)GRID - 1u) {
            double total = atomicAdd(&g_acc, 0.0);
            out[0] = (float)(total / (double)NTRIP);
            // reset state for the next graph replay (all blocks already arrived)
            g_acc  = 0.0;
            g_done = 0u;
            g_sync = 0u;
            __threadfence();
        }
    }
}

extern "C" void kernel_launch(void* const* d_in, const int* in_sizes, int n_in,
                              void* d_out, int out_size) {
    // Resolve input ordering by element count (x: 4194304, trip: 600000)
    const float* x;
    const void*  trip;
    if (in_sizes[0] == NROWS * DIM) { x = (const float*)d_in[0]; trip = d_in[1]; }
    else                            { x = (const float*)d_in[1]; trip = d_in[0]; }

    float* out = (float*)d_out;

    fused_kernel<<<GRID, 256>>>(x, trip, out);
}